// round 6
// baseline (speedup 1.0000x reference)
#include <cuda_runtime.h>
#include <cuda_fp16.h>
#include <stdint.h>

// Problem constants
#define N_GENES 20000
#define N_DRUGS 4000
#define IN_C    1024
#define OUT_C   512
#define N_EDGES 262144
#define MROWS   20096   // padded row capacity (157 * 128)

// ---------------- device scratch ----------------
__device__ int      g_row_deg[N_GENES];
__device__ int      g_col_deg[N_DRUGS];
__device__ int      g_offs[N_DRUGS];
__device__ int      g_cursor[N_DRUGS];
__device__ int      g_active[N_GENES];
__device__ int      g_rowmap[N_GENES];
__device__ float    g_rowscale[N_GENES];
__device__ int      g_nactive;
__device__ int      g_is64;
__device__ uint32_t g_xph[(size_t)MROWS * 512];   // X bf16x2 hi plane (k-pairs)
__device__ uint32_t g_xpl[(size_t)MROWS * 512];   // X bf16x2 lo plane
__device__ uint32_t g_wph[512 * 512];             // W^T bf16x2 hi plane [n][kw]
__device__ uint32_t g_wpl[512 * 512];             // W^T bf16x2 lo plane
__device__ __half   g_xw16[(size_t)MROWS * OUT_C]; // row-scaled XW, fp16
__device__ int      g_sidx[N_EDGES];

// ---------------- helpers ----------------
__device__ __forceinline__ uint32_t smem_u32(const void* p) {
    uint32_t a;
    asm("{ .reg .u64 t; cvta.to.shared.u64 t, %1; cvt.u32.u64 %0, t; }"
        : "=r"(a) : "l"(p));
    return a;
}

__device__ __forceinline__ void split2_bf16(float f0, float f1,
                                            uint32_t& h, uint32_t& l) {
    asm("cvt.rn.bf16x2.f32 %0, %1, %2;" : "=r"(h) : "f"(f1), "f"(f0));
    float r0 = f0 - __uint_as_float(h << 16);
    float r1 = f1 - __uint_as_float(h & 0xffff0000u);
    asm("cvt.rn.bf16x2.f32 %0, %1, %2;" : "=r"(l) : "f"(r1), "f"(r0));
}

__device__ __forceinline__ void mma_bf16(float* c, const uint32_t* a, const uint32_t* b) {
    asm volatile(
        "mma.sync.aligned.m16n8k16.row.col.f32.bf16.bf16.f32 "
        "{%0,%1,%2,%3}, {%4,%5,%6,%7}, {%8,%9}, {%0,%1,%2,%3};"
        : "+f"(c[0]), "+f"(c[1]), "+f"(c[2]), "+f"(c[3])
        : "r"(a[0]), "r"(a[1]), "r"(a[2]), "r"(a[3]), "r"(b[0]), "r"(b[1]));
}

__device__ __forceinline__ void ldm_x4(uint32_t* r, uint32_t addr) {
    asm volatile("ldmatrix.sync.aligned.m8n8.x4.shared.b16 {%0,%1,%2,%3}, [%4];"
                 : "=r"(r[0]), "=r"(r[1]), "=r"(r[2]), "=r"(r[3]) : "r"(addr));
}

__device__ __forceinline__ void ldm_x2(uint32_t* r, uint32_t addr) {
    asm volatile("ldmatrix.sync.aligned.m8n8.x2.shared.b16 {%0,%1}, [%2];"
                 : "=r"(r[0]), "=r"(r[1]) : "r"(addr));
}

__device__ __forceinline__ void cp16(uint32_t dst, const void* src) {
    asm volatile("cp.async.cg.shared.global [%0], [%1], 16;"
                 :: "r"(dst), "l"(src) : "memory");
}
#define CP_COMMIT() asm volatile("cp.async.commit_group;" ::: "memory")
#define CP_WAIT1()  asm volatile("cp.async.wait_group 1;" ::: "memory")
#define CP_WAIT0()  asm volatile("cp.async.wait_group 0;" ::: "memory")

__device__ __forceinline__ void load_edge(const void* ei, int e, int& s, int& d) {
    if (g_is64) {
        const long long* p = (const long long*)ei;
        s = (int)p[e];
        d = (int)p[N_EDGES + e];
    } else {
        const int* p = (const int*)ei;
        s = p[e];
        d = p[N_EDGES + e];
    }
}

// ---------------- preprocessing ----------------
// fused: zero arrays + detect edge dtype (block 0)
__global__ void k_init(const int* __restrict__ ei32) {
    int i = blockIdx.x * blockDim.x + threadIdx.x;
    if (i < N_GENES) g_row_deg[i] = 0;
    if (i < N_DRUGS) { g_col_deg[i] = 0; g_cursor[i] = 0; }
    if (i == 0) g_nactive = 0;
    if (blockIdx.x == 0) {
        __shared__ int any_nonzero;
        if (threadIdx.x == 0) any_nonzero = 0;
        __syncthreads();
        for (int j = threadIdx.x * 2 + 1; j < 8192; j += blockDim.x * 2)
            if (ei32[j] != 0) any_nonzero = 1;
        __syncthreads();
        if (threadIdx.x == 0) g_is64 = any_nonzero ? 0 : 1;
    }
}

__global__ void k_degree(const void* __restrict__ ei) {
    int e = blockIdx.x * blockDim.x + threadIdx.x;
    if (e >= N_EDGES) return;
    int s, d;
    load_edge(ei, e, s, d);
    if (s >= 0 && s < N_GENES) atomicAdd(&g_row_deg[s], 1);
    if (d >= 0 && d < N_DRUGS) atomicAdd(&g_col_deg[d], 1);
}

// fused: compact genes (blocks 0..19) + exclusive scan of col_deg (block 20)
__global__ void k_compact_scan() {
    if (blockIdx.x < 20) {
        int g = blockIdx.x * 1024 + threadIdx.x;
        if (g >= N_GENES) return;
        int deg = g_row_deg[g];
        if (deg > 0) {
            int idx = atomicAdd(&g_nactive, 1);
            g_active[idx] = g;
            g_rowmap[g] = idx;
            g_rowscale[idx] = rsqrtf((float)deg);
        }
    } else {
        __shared__ int sh[1024];
        int t = threadIdx.x;
        int base = t * 4;
        int v[4];
        int sum = 0;
#pragma unroll
        for (int i = 0; i < 4; i++) {
            v[i] = (base + i < N_DRUGS) ? g_col_deg[base + i] : 0;
            sum += v[i];
        }
        sh[t] = sum;
        __syncthreads();
        for (int d = 1; d < 1024; d <<= 1) {
            int x = (t >= d) ? sh[t - d] : 0;
            __syncthreads();
            sh[t] += x;
            __syncthreads();
        }
        int run = (t > 0) ? sh[t - 1] : 0;
#pragma unroll
        for (int i = 0; i < 4; i++) {
            if (base + i < N_DRUGS) {
                g_offs[base + i] = run;
                run += v[i];
            }
        }
    }
}

__global__ void k_place(const void* __restrict__ ei) {
    int e = blockIdx.x * blockDim.x + threadIdx.x;
    if (e >= N_EDGES) return;
    int s, d;
    load_edge(ei, e, s, d);
    if (s < 0 || s >= N_GENES || d < 0 || d >= N_DRUGS) return;
    int p = g_offs[d] + atomicAdd(&g_cursor[d], 1);
    g_sidx[p] = g_rowmap[s];
}

// ---------------- pre-split kernels ----------------
// W [1024 k][512 n] -> Wp[n][kw] bf16x2 hi/lo
__global__ void k_split_w(const float* __restrict__ W) {
    int id = blockIdx.x * blockDim.x + threadIdx.x;   // 262144
    int kw = id >> 9;        // 0..511
    int n = id & 511;
    float f0 = W[(size_t)(2 * kw) * OUT_C + n];
    float f1 = W[(size_t)(2 * kw + 1) * OUT_C + n];
    uint32_t h, l;
    split2_bf16(f0, f1, h, l);
    g_wph[n * 512 + kw] = h;
    g_wpl[n * 512 + kw] = l;
}

// X compact rows -> Xp[r][kw] bf16x2 hi/lo
__global__ void k_split_x(const float* __restrict__ X) {
    int r = blockIdx.x;
    if (r >= g_nactive) return;
    const float* src = X + (size_t)g_active[r] * IN_C;
#pragma unroll
    for (int q = 0; q < 2; q++) {
        int kw = threadIdx.x + q * 256;
        float2 f = *(const float2*)(src + 2 * kw);
        uint32_t h, l;
        split2_bf16(f.x, f.y, h, l);
        g_xph[(size_t)r * 512 + kw] = h;
        g_xpl[(size_t)r * 512 + kw] = l;
    }
}

// ---------------- bf16x3 tensor GEMM with cp.async + ldmatrix ----------------
// CTA 128x128, KT=32 (16 kwords), smem rows padded to 20 words (conflict-free).
#define GM 128
#define GN 128
#define NKT 32
#define ROW_W 20
#define PLANE_B (128 * ROW_W * 4)     // 10240
#define AHI_B 0
#define ALO_B PLANE_B
#define BHI_B (2 * PLANE_B)
#define BLO_B (3 * PLANE_B)
#define BUF_B (4 * PLANE_B)           // 40960
#define GEMM_SMEM (2 * BUF_B)         // 81920

__global__ __launch_bounds__(256) void k_gemm(void) {
    const int nact = g_nactive;
    const int m0 = blockIdx.y * GM;
    if (m0 >= nact) return;
    const int n0 = blockIdx.x * GN;

    extern __shared__ __align__(128) uint32_t smem[];
    const uint32_t sb = smem_u32(smem);

    const int tid = threadIdx.x;
    const int wid = tid >> 5;
    const int lane = tid & 31;
    const int g = lane >> 2;
    const int tig = lane & 3;
    const int mwarp = (wid & 1) * 64;
    const int nwarp = (wid >> 1) * 32;

    // staging: i in {0,1}: idx -> row (0..127), blk (0..3)
    uint32_t dstoff[2];
    const uint32_t *sAh[2], *sAl[2], *sBh[2], *sBl[2];
#pragma unroll
    for (int i = 0; i < 2; i++) {
        int idx = i * 256 + tid;
        int row = idx >> 2, blk = idx & 3;
        dstoff[i] = (uint32_t)(row * ROW_W + blk * 4) * 4;
        sAh[i] = g_xph + (size_t)(m0 + row) * 512 + blk * 4;
        sAl[i] = g_xpl + (size_t)(m0 + row) * 512 + blk * 4;
        sBh[i] = g_wph + (size_t)(n0 + row) * 512 + blk * 4;
        sBl[i] = g_wpl + (size_t)(n0 + row) * 512 + blk * 4;
    }

    // ldmatrix lane addresses (byte offsets within a buffer)
    const int amat = lane >> 3;
    const int aq = (amat & 1) * 8 + (lane & 7);
    const int akq = (amat >> 1) * 4;
    const uint32_t aBase = sb + (uint32_t)((mwarp + aq) * ROW_W + akq) * 4;
    const int ql = lane & 15;
    const int bq = ql & 7;
    const int bmat = ql >> 3;
    const uint32_t bBase = sb + (uint32_t)((nwarp + bq) * ROW_W + bmat * 4) * 4;

    float acc[4][4][4];
#pragma unroll
    for (int i = 0; i < 4; i++)
#pragma unroll
        for (int j = 0; j < 4; j++)
#pragma unroll
            for (int r = 0; r < 4; r++) acc[i][j][r] = 0.f;

    // prologue: issue tile 0 into buffer 0
#pragma unroll
    for (int i = 0; i < 2; i++) {
        cp16(sb + AHI_B + dstoff[i], sAh[i]);
        cp16(sb + ALO_B + dstoff[i], sAl[i]);
        cp16(sb + BHI_B + dstoff[i], sBh[i]);
        cp16(sb + BLO_B + dstoff[i], sBl[i]);
    }
    CP_COMMIT();

#pragma unroll 1
    for (int kt = 0; kt < NKT; kt++) {
        const uint32_t bufo = (kt & 1) * BUF_B;
        if (kt + 1 < NKT) {
            const uint32_t nbufo = ((kt + 1) & 1) * BUF_B;
            const int koff = (kt + 1) * 16;
#pragma unroll
            for (int i = 0; i < 2; i++) {
                cp16(sb + nbufo + AHI_B + dstoff[i], sAh[i] + koff);
                cp16(sb + nbufo + ALO_B + dstoff[i], sAl[i] + koff);
                cp16(sb + nbufo + BHI_B + dstoff[i], sBh[i] + koff);
                cp16(sb + nbufo + BLO_B + dstoff[i], sBl[i] + koff);
            }
            CP_COMMIT();
            CP_WAIT1();
        } else {
            CP_WAIT0();
        }
        __syncthreads();

#pragma unroll
        for (int ks = 0; ks < 2; ks++) {
            const uint32_t kso = ks * 32;   // 8 words
            uint32_t ah[4][4], al[4][4], bh[4][2], bl[4][2];
#pragma unroll
            for (int mf = 0; mf < 4; mf++) {
                uint32_t a = aBase + bufo + mf * (16 * ROW_W * 4) + kso;
                ldm_x4(ah[mf], a + AHI_B);
                ldm_x4(al[mf], a + ALO_B);
            }
#pragma unroll
            for (int nf = 0; nf < 4; nf++) {
                uint32_t b = bBase + bufo + nf * (8 * ROW_W * 4) + kso;
                ldm_x2(bh[nf], b + BHI_B);
                ldm_x2(bl[nf], b + BLO_B);
            }
#pragma unroll
            for (int mf = 0; mf < 4; mf++) {
#pragma unroll
                for (int nf = 0; nf < 4; nf++) {
                    mma_bf16(acc[mf][nf], ah[mf], bh[nf]);
                    mma_bf16(acc[mf][nf], ah[mf], bl[nf]);
                    mma_bf16(acc[mf][nf], al[mf], bh[nf]);
                }
            }
        }
        __syncthreads();
    }

    // epilogue: row scale, fp16 store
#pragma unroll
    for (int mf = 0; mf < 4; mf++) {
        int r0 = m0 + mwarp + mf * 16 + g;
        int r1 = r0 + 8;
#pragma unroll
        for (int nf = 0; nf < 4; nf++) {
            int col = n0 + nwarp + nf * 8 + tig * 2;
            if (r0 < nact) {
                float s0 = g_rowscale[r0];
                __half2 h = __float22half2_rn(
                    make_float2(acc[mf][nf][0] * s0, acc[mf][nf][1] * s0));
                *(__half2*)&g_xw16[(size_t)r0 * OUT_C + col] = h;
            }
            if (r1 < nact) {
                float s1 = g_rowscale[r1];
                __half2 h = __float22half2_rn(
                    make_float2(acc[mf][nf][2] * s1, acc[mf][nf][3] * s1));
                *(__half2*)&g_xw16[(size_t)r1 * OUT_C + col] = h;
            }
        }
    }
}

// ---------------- aggregation (fp16 gather, fp32 accumulate) ----------------
__device__ __forceinline__ void addv(float* acc, uint4 v) {
    const __half2* h = (const __half2*)&v;
#pragma unroll
    for (int j = 0; j < 4; j++) {
        float2 f = __half22float2(h[j]);
        acc[2 * j] += f.x;
        acc[2 * j + 1] += f.y;
    }
}

__global__ __launch_bounds__(64) void k_aggregate(const float* __restrict__ bias,
                                                  float* __restrict__ out) {
    int d = blockIdx.x;
    int t = threadIdx.x;       // 64 threads, 8 channels each
    int beg = g_offs[d];
    int n = g_col_deg[d];
    int end = beg + n;
    const uint4* xw = (const uint4*)g_xw16;   // row = 64 uint4

    float acc[8] = {0.f, 0.f, 0.f, 0.f, 0.f, 0.f, 0.f, 0.f};
    int i = beg;
    for (; i + 3 < end; i += 4) {
        int s0 = g_sidx[i], s1 = g_sidx[i + 1], s2 = g_sidx[i + 2], s3 = g_sidx[i + 3];
        uint4 v0 = xw[(size_t)s0 * 64 + t];
        uint4 v1 = xw[(size_t)s1 * 64 + t];
        uint4 v2 = xw[(size_t)s2 * 64 + t];
        uint4 v3 = xw[(size_t)s3 * 64 + t];
        addv(acc, v0);
        addv(acc, v1);
        addv(acc, v2);
        addv(acc, v3);
    }
    for (; i < end; i++) {
        uint4 v0 = xw[(size_t)g_sidx[i] * 64 + t];
        addv(acc, v0);
    }
    float cs = (n > 0) ? rsqrtf((float)n) : 0.f;
    float4 b0 = ((const float4*)bias)[t * 2];
    float4 b1 = ((const float4*)bias)[t * 2 + 1];
    float4 o0 = make_float4(acc[0] * cs + b0.x, acc[1] * cs + b0.y,
                            acc[2] * cs + b0.z, acc[3] * cs + b0.w);
    float4 o1 = make_float4(acc[4] * cs + b1.x, acc[5] * cs + b1.y,
                            acc[6] * cs + b1.z, acc[7] * cs + b1.w);
    ((float4*)out)[(size_t)d * 128 + t * 2] = o0;
    ((float4*)out)[(size_t)d * 128 + t * 2 + 1] = o1;
}

// ---------------- launch ----------------
extern "C" void kernel_launch(void* const* d_in, const int* in_sizes, int n_in,
                              void* d_out, int out_size) {
    const float* x = (const float*)d_in[0];
    const float* w = (const float*)d_in[1];
    const float* bias = (const float*)d_in[2];
    const void* ei = d_in[3];
    float* out = (float*)d_out;

    static bool attr_set = false;
    if (!attr_set) {
        cudaFuncSetAttribute(k_gemm, cudaFuncAttributeMaxDynamicSharedMemorySize,
                             GEMM_SMEM);
        attr_set = true;
    }

    k_init<<<(N_GENES + 255) / 256, 256>>>((const int*)ei);
    k_degree<<<(N_EDGES + 255) / 256, 256>>>(ei);
    k_compact_scan<<<21, 1024>>>();
    k_split_w<<<(512 * 512) / 256, 256>>>(w);
    k_split_x<<<N_GENES, 256>>>(x);
    k_place<<<(N_EDGES + 255) / 256, 256>>>(ei);

    dim3 gemm_grid(OUT_C / GN, (MROWS) / GM);
    k_gemm<<<gemm_grid, 256, GEMM_SMEM>>>();

    k_aggregate<<<N_DRUGS, 64>>>(bias, out);
}

// round 7
// speedup vs baseline: 1.3789x; 1.3789x over previous
#include <cuda_runtime.h>
#include <cuda_fp16.h>
#include <stdint.h>

// Problem constants
#define N_GENES 20000
#define N_DRUGS 4000
#define IN_C    1024
#define OUT_C   512
#define N_EDGES 262144
#define MROWS   20096          // padded rows (157 * 128)
#define MB      (MROWS / 16)   // 1256 A row-blocks
#define KB      64             // k16 blocks (1024/16)

// ---------------- device scratch ----------------
__device__ int      g_row_deg[N_GENES];
__device__ int      g_col_deg[N_DRUGS];
__device__ int      g_offs[N_DRUGS];
__device__ int      g_cursor[N_DRUGS];
__device__ int      g_active[N_GENES];
__device__ int      g_rowmap[N_GENES];
__device__ float    g_rowscale[N_GENES];
__device__ int      g_nactive;
__device__ int      g_is64;
// fragment-layout bf16x2 planes: A block (mb,kb) = 128 words (lane*4+slot)
__device__ uint32_t g_xfh[(size_t)MB * KB * 128];
__device__ uint32_t g_xfl[(size_t)MB * KB * 128];
// B block (nb,kb) = 64 words (lane*2+slot); 64 nb
__device__ uint32_t g_wfh[64 * KB * 64];
__device__ uint32_t g_wfl[64 * KB * 64];
__device__ __half   g_xw16[(size_t)MROWS * OUT_C];
__device__ int      g_sidx[N_EDGES];

// ---------------- helpers ----------------
__device__ __forceinline__ void split2_bf16(float f0, float f1,
                                            uint32_t& h, uint32_t& l) {
    asm("cvt.rn.bf16x2.f32 %0, %1, %2;" : "=r"(h) : "f"(f1), "f"(f0));
    float r0 = f0 - __uint_as_float(h << 16);
    float r1 = f1 - __uint_as_float(h & 0xffff0000u);
    asm("cvt.rn.bf16x2.f32 %0, %1, %2;" : "=r"(l) : "f"(r1), "f"(r0));
}

__device__ __forceinline__ void mma_bf16(float* c, const uint32_t* a, const uint32_t* b) {
    asm volatile(
        "mma.sync.aligned.m16n8k16.row.col.f32.bf16.bf16.f32 "
        "{%0,%1,%2,%3}, {%4,%5,%6,%7}, {%8,%9}, {%0,%1,%2,%3};"
        : "+f"(c[0]), "+f"(c[1]), "+f"(c[2]), "+f"(c[3])
        : "r"(a[0]), "r"(a[1]), "r"(a[2]), "r"(a[3]), "r"(b[0]), "r"(b[1]));
}

__device__ __forceinline__ void load_edge(const void* ei, int e, int& s, int& d) {
    if (g_is64) {
        const long long* p = (const long long*)ei;
        s = (int)p[e];
        d = (int)p[N_EDGES + e];
    } else {
        const int* p = (const int*)ei;
        s = p[e];
        d = p[N_EDGES + e];
    }
}

// ---------------- preprocessing ----------------
__global__ void k_init(const int* __restrict__ ei32) {
    int i = blockIdx.x * blockDim.x + threadIdx.x;
    if (i < N_GENES) g_row_deg[i] = 0;
    if (i < N_DRUGS) { g_col_deg[i] = 0; g_cursor[i] = 0; }
    if (i == 0) g_nactive = 0;
    if (blockIdx.x == 0) {
        __shared__ int any_nonzero;
        if (threadIdx.x == 0) any_nonzero = 0;
        __syncthreads();
        for (int j = threadIdx.x * 2 + 1; j < 8192; j += blockDim.x * 2)
            if (ei32[j] != 0) any_nonzero = 1;
        __syncthreads();
        if (threadIdx.x == 0) g_is64 = any_nonzero ? 0 : 1;
    }
}

__global__ void k_degree(const void* __restrict__ ei) {
    int e = blockIdx.x * blockDim.x + threadIdx.x;
    if (e >= N_EDGES) return;
    int s, d;
    load_edge(ei, e, s, d);
    if (s >= 0 && s < N_GENES) atomicAdd(&g_row_deg[s], 1);
    if (d >= 0 && d < N_DRUGS) atomicAdd(&g_col_deg[d], 1);
}

__global__ void k_compact_scan() {
    if (blockIdx.x < 20) {
        int g = blockIdx.x * 1024 + threadIdx.x;
        if (g >= N_GENES) return;
        int deg = g_row_deg[g];
        if (deg > 0) {
            int idx = atomicAdd(&g_nactive, 1);
            g_active[idx] = g;
            g_rowmap[g] = idx;
            g_rowscale[idx] = rsqrtf((float)deg);
        }
    } else {
        __shared__ int sh[1024];
        int t = threadIdx.x;
        int base = t * 4;
        int v[4];
        int sum = 0;
#pragma unroll
        for (int i = 0; i < 4; i++) {
            v[i] = (base + i < N_DRUGS) ? g_col_deg[base + i] : 0;
            sum += v[i];
        }
        sh[t] = sum;
        __syncthreads();
        for (int d = 1; d < 1024; d <<= 1) {
            int x = (t >= d) ? sh[t - d] : 0;
            __syncthreads();
            sh[t] += x;
            __syncthreads();
        }
        int run = (t > 0) ? sh[t - 1] : 0;
#pragma unroll
        for (int i = 0; i < 4; i++) {
            if (base + i < N_DRUGS) {
                g_offs[base + i] = run;
                run += v[i];
            }
        }
    }
}

__global__ void k_place(const void* __restrict__ ei) {
    int e = blockIdx.x * blockDim.x + threadIdx.x;
    if (e >= N_EDGES) return;
    int s, d;
    load_edge(ei, e, s, d);
    if (s < 0 || s >= N_GENES || d < 0 || d >= N_DRUGS) return;
    int p = g_offs[d] + atomicAdd(&g_cursor[d], 1);
    g_sidx[p] = g_rowmap[s];
}

// ---------------- split into fragment-layout planes ----------------
// W [1024k][512n] -> B frag planes. id = kw*512 + n (coalesced W reads).
__global__ void k_split_w(const float* __restrict__ W) {
    int id = blockIdx.x * blockDim.x + threadIdx.x;   // 262144
    int kw = id >> 9;
    int n = id & 511;
    float f0 = W[(size_t)(2 * kw) * OUT_C + n];
    float f1 = W[(size_t)(2 * kw + 1) * OUT_C + n];
    uint32_t h, l;
    split2_bf16(f0, f1, h, l);
    int nb = n >> 3, g = n & 7;
    int kb = kw >> 3, wk = kw & 7;
    int lane = g * 4 + (wk & 3);
    int slot = wk >> 2;
    size_t widx = ((size_t)(nb * KB + kb) * 32 + lane) * 2 + slot;
    g_wfh[widx] = h;
    g_wfl[widx] = l;
}

// X active rows -> A frag planes. One block (256 thr) per row.
__global__ void k_split_x(const float* __restrict__ X) {
    int r = blockIdx.x;
    if (r >= g_nactive) return;
    const float* src = X + (size_t)g_active[r] * IN_C;
    int mb = r >> 4, mr = r & 15;
    int half = mr >> 3;       // a1/a3 vs a0/a2
    int g = mr & 7;
#pragma unroll
    for (int q = 0; q < 2; q++) {
        int kw = threadIdx.x + q * 256;
        float2 f = *(const float2*)(src + 2 * kw);
        uint32_t h, l;
        split2_bf16(f.x, f.y, h, l);
        int kb = kw >> 3, wk = kw & 7;
        int lane = g * 4 + (wk & 3);
        int slot = (wk >> 2) * 2 + half;
        size_t widx = ((size_t)(mb * KB + kb) * 32 + lane) * 4 + slot;
        g_xfh[widx] = h;
        g_xfl[widx] = l;
    }
}

// ---------------- zero-staging bf16x3 tensor GEMM ----------------
// CTA 128x128, warps: (wid&1)->64m, (wid>>1)->32n. Pure LDG + MMA.
__global__ __launch_bounds__(256) void k_gemm(void) {
    const int nact = g_nactive;
    const int m0 = blockIdx.y * 128;
    if (m0 >= nact) return;
    const int n0 = blockIdx.x * 128;

    const int tid = threadIdx.x;
    const int wid = tid >> 5;
    const int lane = tid & 31;
    const int g = lane >> 2;
    const int tig = lane & 3;
    const int mwarp = (wid & 1) * 64;
    const int nwarp = (wid >> 1) * 32;
    const int mb0 = (m0 + mwarp) >> 4;
    const int nb0 = (n0 + nwarp) >> 3;

    const uint4* Af_h = (const uint4*)g_xfh;
    const uint4* Af_l = (const uint4*)g_xfl;
    const uint2* Bf_h = (const uint2*)g_wfh;
    const uint2* Bf_l = (const uint2*)g_wfl;

    float acc[4][4][4];
#pragma unroll
    for (int i = 0; i < 4; i++)
#pragma unroll
        for (int j = 0; j < 4; j++)
#pragma unroll
            for (int r = 0; r < 4; r++) acc[i][j][r] = 0.f;

    uint4 ah[2][4], al[2][4];
    uint2 bh[2][4], bl[2][4];

#define LOADK(buf, kb)                                                      \
    do {                                                                    \
        _Pragma("unroll")                                                   \
        for (int mf = 0; mf < 4; mf++) {                                    \
            size_t ai = (size_t)((mb0 + mf) * KB + (kb)) * 32 + lane;       \
            ah[buf][mf] = Af_h[ai];                                         \
            al[buf][mf] = Af_l[ai];                                         \
        }                                                                   \
        _Pragma("unroll")                                                   \
        for (int nf = 0; nf < 4; nf++) {                                    \
            size_t bi = (size_t)((nb0 + nf) * KB + (kb)) * 32 + lane;       \
            bh[buf][nf] = Bf_h[bi];                                         \
            bl[buf][nf] = Bf_l[bi];                                         \
        }                                                                   \
    } while (0)

    LOADK(0, 0);
#pragma unroll 2
    for (int kb = 0; kb < KB; kb++) {
        const int cur = kb & 1;
        const int nxt = cur ^ 1;
        if (kb + 1 < KB) LOADK(nxt, kb + 1);
#pragma unroll
        for (int mf = 0; mf < 4; mf++) {
#pragma unroll
            for (int nf = 0; nf < 4; nf++) {
                mma_bf16(acc[mf][nf], (const uint32_t*)&ah[cur][mf],
                         (const uint32_t*)&bh[cur][nf]);
                mma_bf16(acc[mf][nf], (const uint32_t*)&ah[cur][mf],
                         (const uint32_t*)&bl[cur][nf]);
                mma_bf16(acc[mf][nf], (const uint32_t*)&al[cur][mf],
                         (const uint32_t*)&bh[cur][nf]);
            }
        }
    }
#undef LOADK

    // epilogue: row scale, fp16 store
#pragma unroll
    for (int mf = 0; mf < 4; mf++) {
        int r0 = m0 + mwarp + mf * 16 + g;
        int r1 = r0 + 8;
#pragma unroll
        for (int nf = 0; nf < 4; nf++) {
            int col = n0 + nwarp + nf * 8 + tig * 2;
            if (r0 < nact) {
                float s0 = g_rowscale[r0];
                __half2 h = __float22half2_rn(
                    make_float2(acc[mf][nf][0] * s0, acc[mf][nf][1] * s0));
                *(__half2*)&g_xw16[(size_t)r0 * OUT_C + col] = h;
            }
            if (r1 < nact) {
                float s1 = g_rowscale[r1];
                __half2 h = __float22half2_rn(
                    make_float2(acc[mf][nf][2] * s1, acc[mf][nf][3] * s1));
                *(__half2*)&g_xw16[(size_t)r1 * OUT_C + col] = h;
            }
        }
    }
}

// ---------------- aggregation (fp16 gather, fp32 accumulate) ----------------
__device__ __forceinline__ void addv(float* acc, uint4 v) {
    const __half2* h = (const __half2*)&v;
#pragma unroll
    for (int j = 0; j < 4; j++) {
        float2 f = __half22float2(h[j]);
        acc[2 * j] += f.x;
        acc[2 * j + 1] += f.y;
    }
}

__global__ __launch_bounds__(64) void k_aggregate(const float* __restrict__ bias,
                                                  float* __restrict__ out) {
    int d = blockIdx.x;
    int t = threadIdx.x;
    int beg = g_offs[d];
    int n = g_col_deg[d];
    int end = beg + n;
    const uint4* xw = (const uint4*)g_xw16;

    float acc[8] = {0.f, 0.f, 0.f, 0.f, 0.f, 0.f, 0.f, 0.f};
    int i = beg;
    for (; i + 3 < end; i += 4) {
        int s0 = g_sidx[i], s1 = g_sidx[i + 1], s2 = g_sidx[i + 2], s3 = g_sidx[i + 3];
        uint4 v0 = xw[(size_t)s0 * 64 + t];
        uint4 v1 = xw[(size_t)s1 * 64 + t];
        uint4 v2 = xw[(size_t)s2 * 64 + t];
        uint4 v3 = xw[(size_t)s3 * 64 + t];
        addv(acc, v0);
        addv(acc, v1);
        addv(acc, v2);
        addv(acc, v3);
    }
    for (; i < end; i++) {
        uint4 v0 = xw[(size_t)g_sidx[i] * 64 + t];
        addv(acc, v0);
    }
    float cs = (n > 0) ? rsqrtf((float)n) : 0.f;
    float4 b0 = ((const float4*)bias)[t * 2];
    float4 b1 = ((const float4*)bias)[t * 2 + 1];
    float4 o0 = make_float4(acc[0] * cs + b0.x, acc[1] * cs + b0.y,
                            acc[2] * cs + b0.z, acc[3] * cs + b0.w);
    float4 o1 = make_float4(acc[4] * cs + b1.x, acc[5] * cs + b1.y,
                            acc[6] * cs + b1.z, acc[7] * cs + b1.w);
    ((float4*)out)[(size_t)d * 128 + t * 2] = o0;
    ((float4*)out)[(size_t)d * 128 + t * 2 + 1] = o1;
}

// ---------------- launch ----------------
extern "C" void kernel_launch(void* const* d_in, const int* in_sizes, int n_in,
                              void* d_out, int out_size) {
    const float* x = (const float*)d_in[0];
    const float* w = (const float*)d_in[1];
    const float* bias = (const float*)d_in[2];
    const void* ei = d_in[3];
    float* out = (float*)d_out;

    k_init<<<(N_GENES + 255) / 256, 256>>>((const int*)ei);
    k_degree<<<(N_EDGES + 255) / 256, 256>>>(ei);
    k_compact_scan<<<21, 1024>>>();
    k_split_x<<<N_GENES, 256>>>(x);
    k_split_w<<<(512 * 512) / 256, 256>>>(w);
    k_place<<<(N_EDGES + 255) / 256, 256>>>(ei);

    dim3 gemm_grid(OUT_C / 128, MROWS / 128);
    k_gemm<<<gemm_grid, 256>>>();

    k_aggregate<<<N_DRUGS, 64>>>(bias, out);
}

// round 8
// speedup vs baseline: 1.4873x; 1.0787x over previous
#include <cuda_runtime.h>
#include <cuda_fp16.h>
#include <stdint.h>

// Problem constants
#define N_GENES 20000
#define N_DRUGS 4000
#define IN_C    1024
#define OUT_C   512
#define N_EDGES 262144
#define MROWS   20096          // padded rows (157 * 128)
#define MB      (MROWS / 16)   // 1256 A row-blocks
#define KB      64             // k16 blocks (1024/16)

// ---------------- device scratch ----------------
__device__ int      g_row_deg[N_GENES];
__device__ int      g_col_deg[N_DRUGS];
__device__ int      g_offs[N_DRUGS];
__device__ int      g_cursor[N_DRUGS];
__device__ int      g_active[N_GENES];
__device__ int      g_rowmap[N_GENES];
__device__ float    g_rowscale[N_GENES];
__device__ int      g_nactive;
__device__ int      g_is64;
// fragment-layout bf16x2 planes: A block (mb,kb) = 128 words (lane*4+slot)
__device__ uint32_t g_xfh[(size_t)MB * KB * 128];
__device__ uint32_t g_xfl[(size_t)MB * KB * 128];
// B block (nb,kb) = 64 words (lane*2+slot); 64 nb
__device__ uint32_t g_wfh[64 * KB * 64];
__device__ uint32_t g_wfl[64 * KB * 64];
__device__ __half   g_xw16[(size_t)MROWS * OUT_C];
__device__ int      g_sidx[N_EDGES];

// ---------------- helpers ----------------
__device__ __forceinline__ void split2_bf16(float f0, float f1,
                                            uint32_t& h, uint32_t& l) {
    asm("cvt.rn.bf16x2.f32 %0, %1, %2;" : "=r"(h) : "f"(f1), "f"(f0));
    float r0 = f0 - __uint_as_float(h << 16);
    float r1 = f1 - __uint_as_float(h & 0xffff0000u);
    asm("cvt.rn.bf16x2.f32 %0, %1, %2;" : "=r"(l) : "f"(r1), "f"(r0));
}

__device__ __forceinline__ void mma_bf16(float* c, const uint32_t* a, const uint32_t* b) {
    asm volatile(
        "mma.sync.aligned.m16n8k16.row.col.f32.bf16.bf16.f32 "
        "{%0,%1,%2,%3}, {%4,%5,%6,%7}, {%8,%9}, {%0,%1,%2,%3};"
        : "+f"(c[0]), "+f"(c[1]), "+f"(c[2]), "+f"(c[3])
        : "r"(a[0]), "r"(a[1]), "r"(a[2]), "r"(a[3]), "r"(b[0]), "r"(b[1]));
}

__device__ __forceinline__ void load_edge(const void* ei, int e, int& s, int& d) {
    if (g_is64) {
        const long long* p = (const long long*)ei;
        s = (int)p[e];
        d = (int)p[N_EDGES + e];
    } else {
        const int* p = (const int*)ei;
        s = p[e];
        d = p[N_EDGES + e];
    }
}

// ---------------- preprocessing ----------------
__global__ void k_init(const int* __restrict__ ei32) {
    int i = blockIdx.x * blockDim.x + threadIdx.x;
    if (i < N_GENES) g_row_deg[i] = 0;
    if (i < N_DRUGS) { g_col_deg[i] = 0; g_cursor[i] = 0; }
    if (i == 0) g_nactive = 0;
    if (blockIdx.x == 0) {
        __shared__ int any_nonzero;
        if (threadIdx.x == 0) any_nonzero = 0;
        __syncthreads();
        for (int j = threadIdx.x * 2 + 1; j < 8192; j += blockDim.x * 2)
            if (ei32[j] != 0) any_nonzero = 1;
        __syncthreads();
        if (threadIdx.x == 0) g_is64 = any_nonzero ? 0 : 1;
    }
}

__global__ void k_degree(const void* __restrict__ ei) {
    int e = blockIdx.x * blockDim.x + threadIdx.x;
    if (e >= N_EDGES) return;
    int s, d;
    load_edge(ei, e, s, d);
    if (s >= 0 && s < N_GENES) atomicAdd(&g_row_deg[s], 1);
    if (d >= 0 && d < N_DRUGS) atomicAdd(&g_col_deg[d], 1);
}

__global__ void k_compact_scan() {
    if (blockIdx.x < 20) {
        int g = blockIdx.x * 1024 + threadIdx.x;
        if (g >= N_GENES) return;
        int deg = g_row_deg[g];
        if (deg > 0) {
            int idx = atomicAdd(&g_nactive, 1);
            g_active[idx] = g;
            g_rowmap[g] = idx;
            g_rowscale[idx] = rsqrtf((float)deg);
        }
    } else {
        __shared__ int sh[1024];
        int t = threadIdx.x;
        int base = t * 4;
        int v[4];
        int sum = 0;
#pragma unroll
        for (int i = 0; i < 4; i++) {
            v[i] = (base + i < N_DRUGS) ? g_col_deg[base + i] : 0;
            sum += v[i];
        }
        sh[t] = sum;
        __syncthreads();
        for (int d = 1; d < 1024; d <<= 1) {
            int x = (t >= d) ? sh[t - d] : 0;
            __syncthreads();
            sh[t] += x;
            __syncthreads();
        }
        int run = (t > 0) ? sh[t - 1] : 0;
#pragma unroll
        for (int i = 0; i < 4; i++) {
            if (base + i < N_DRUGS) {
                g_offs[base + i] = run;
                run += v[i];
            }
        }
    }
}

__global__ void k_place(const void* __restrict__ ei) {
    int e = blockIdx.x * blockDim.x + threadIdx.x;
    if (e >= N_EDGES) return;
    int s, d;
    load_edge(ei, e, s, d);
    if (s < 0 || s >= N_GENES || d < 0 || d >= N_DRUGS) return;
    int p = g_offs[d] + atomicAdd(&g_cursor[d], 1);
    g_sidx[p] = g_rowmap[s];
}

// ---------------- output-centric split kernels ----------------
// X active rows -> A frag planes. One block per mb (16 rows); thread owns
// one uint4 frag word-group per iteration; stores fully coalesced.
__global__ __launch_bounds__(256) void k_split_x(const float* __restrict__ X) {
    const int mb = blockIdx.x;
    const int m0 = mb * 16;
    const int nact = g_nactive;
    if (m0 >= nact) return;
    const int t = threadIdx.x;
    const int lane = t & 31;
    const int w = t >> 5;            // 0..7: kb phase
    const int g = lane >> 2;
    const int kl = lane & 3;
    const int r0 = m0 + g;
    const int r1 = r0 + 8;
    const float* p0 = (r0 < nact) ? X + (size_t)g_active[r0] * IN_C : 0;
    const float* p1 = (r1 < nact) ? X + (size_t)g_active[r1] * IN_C : 0;
    const float2 z2 = make_float2(0.f, 0.f);
#pragma unroll
    for (int i = 0; i < 8; i++) {
        int kb = i * 8 + w;
        int kwA = kb * 8 + kl;        // word index (pair of floats)
        float2 x0a = p0 ? *(const float2*)(p0 + 2 * kwA) : z2;
        float2 x0b = p0 ? *(const float2*)(p0 + 2 * kwA + 8) : z2;
        float2 x1a = p1 ? *(const float2*)(p1 + 2 * kwA) : z2;
        float2 x1b = p1 ? *(const float2*)(p1 + 2 * kwA + 8) : z2;
        uint4 h, l;
        split2_bf16(x0a.x, x0a.y, h.x, l.x);   // slot0: r0, kwA
        split2_bf16(x1a.x, x1a.y, h.y, l.y);   // slot1: r1, kwA
        split2_bf16(x0b.x, x0b.y, h.z, l.z);   // slot2: r0, kwA+4
        split2_bf16(x1b.x, x1b.y, h.w, l.w);   // slot3: r1, kwA+4
        size_t o = (size_t)(mb * KB + kb) * 32 + lane;
        ((uint4*)g_xfh)[o] = h;
        ((uint4*)g_xfl)[o] = l;
    }
}

// W [1024k][512n] -> B frag planes. Thread owns one uint2 per plane.
__global__ __launch_bounds__(256) void k_split_w(const float* __restrict__ W) {
    int id = blockIdx.x * blockDim.x + threadIdx.x;   // 64*64*32 = 131072
    int lane = id & 31;
    int kb = (id >> 5) & 63;
    int nb = id >> 11;
    int n = nb * 8 + (lane >> 2);
    int kw = kb * 8 + (lane & 3);
    float fa0 = W[(size_t)(2 * kw) * OUT_C + n];
    float fa1 = W[(size_t)(2 * kw + 1) * OUT_C + n];
    float fb0 = W[(size_t)(2 * kw + 8) * OUT_C + n];
    float fb1 = W[(size_t)(2 * kw + 9) * OUT_C + n];
    uint2 h, l;
    split2_bf16(fa0, fa1, h.x, l.x);    // slot0: kw
    split2_bf16(fb0, fb1, h.y, l.y);    // slot1: kw+4
    size_t o = (size_t)(nb * KB + kb) * 32 + lane;
    ((uint2*)g_wfh)[o] = h;
    ((uint2*)g_wfl)[o] = l;
}

// ---------------- zero-staging bf16x3 tensor GEMM ----------------
__global__ __launch_bounds__(256) void k_gemm(void) {
    const int nact = g_nactive;
    const int m0 = blockIdx.y * 128;
    if (m0 >= nact) return;
    const int n0 = blockIdx.x * 128;

    const int tid = threadIdx.x;
    const int wid = tid >> 5;
    const int lane = tid & 31;
    const int g = lane >> 2;
    const int tig = lane & 3;
    const int mwarp = (wid & 1) * 64;
    const int nwarp = (wid >> 1) * 32;
    const int mb0 = (m0 + mwarp) >> 4;
    const int nb0 = (n0 + nwarp) >> 3;

    const uint4* Af_h = (const uint4*)g_xfh;
    const uint4* Af_l = (const uint4*)g_xfl;
    const uint2* Bf_h = (const uint2*)g_wfh;
    const uint2* Bf_l = (const uint2*)g_wfl;

    float acc[4][4][4];
#pragma unroll
    for (int i = 0; i < 4; i++)
#pragma unroll
        for (int j = 0; j < 4; j++)
#pragma unroll
            for (int r = 0; r < 4; r++) acc[i][j][r] = 0.f;

    uint4 ah[2][4], al[2][4];
    uint2 bh[2][4], bl[2][4];

#define LOADK(buf, kb)                                                      \
    do {                                                                    \
        _Pragma("unroll")                                                   \
        for (int mf = 0; mf < 4; mf++) {                                    \
            size_t ai = (size_t)((mb0 + mf) * KB + (kb)) * 32 + lane;       \
            ah[buf][mf] = Af_h[ai];                                         \
            al[buf][mf] = Af_l[ai];                                         \
        }                                                                   \
        _Pragma("unroll")                                                   \
        for (int nf = 0; nf < 4; nf++) {                                    \
            size_t bi = (size_t)((nb0 + nf) * KB + (kb)) * 32 + lane;       \
            bh[buf][nf] = Bf_h[bi];                                         \
            bl[buf][nf] = Bf_l[bi];                                         \
        }                                                                   \
    } while (0)

    LOADK(0, 0);
#pragma unroll 2
    for (int kb = 0; kb < KB; kb++) {
        const int cur = kb & 1;
        const int nxt = cur ^ 1;
        if (kb + 1 < KB) LOADK(nxt, kb + 1);
#pragma unroll
        for (int mf = 0; mf < 4; mf++) {
#pragma unroll
            for (int nf = 0; nf < 4; nf++) {
                mma_bf16(acc[mf][nf], (const uint32_t*)&ah[cur][mf],
                         (const uint32_t*)&bh[cur][nf]);
                mma_bf16(acc[mf][nf], (const uint32_t*)&ah[cur][mf],
                         (const uint32_t*)&bl[cur][nf]);
                mma_bf16(acc[mf][nf], (const uint32_t*)&al[cur][mf],
                         (const uint32_t*)&bh[cur][nf]);
            }
        }
    }
#undef LOADK

    // epilogue: row scale, fp16 store
#pragma unroll
    for (int mf = 0; mf < 4; mf++) {
        int r0 = m0 + mwarp + mf * 16 + g;
        int r1 = r0 + 8;
#pragma unroll
        for (int nf = 0; nf < 4; nf++) {
            int col = n0 + nwarp + nf * 8 + tig * 2;
            if (r0 < nact) {
                float s0 = g_rowscale[r0];
                __half2 h = __float22half2_rn(
                    make_float2(acc[mf][nf][0] * s0, acc[mf][nf][1] * s0));
                *(__half2*)&g_xw16[(size_t)r0 * OUT_C + col] = h;
            }
            if (r1 < nact) {
                float s1 = g_rowscale[r1];
                __half2 h = __float22half2_rn(
                    make_float2(acc[mf][nf][2] * s1, acc[mf][nf][3] * s1));
                *(__half2*)&g_xw16[(size_t)r1 * OUT_C + col] = h;
            }
        }
    }
}

// ---------------- aggregation (fp16 gather, fp32 accumulate) ----------------
__device__ __forceinline__ void addv(float* acc, uint4 v) {
    const __half2* h = (const __half2*)&v;
#pragma unroll
    for (int j = 0; j < 4; j++) {
        float2 f = __half22float2(h[j]);
        acc[2 * j] += f.x;
        acc[2 * j + 1] += f.y;
    }
}

__global__ __launch_bounds__(64) void k_aggregate(const float* __restrict__ bias,
                                                  float* __restrict__ out) {
    int d = blockIdx.x;
    int t = threadIdx.x;
    int beg = g_offs[d];
    int n = g_col_deg[d];
    int end = beg + n;
    const uint4* xw = (const uint4*)g_xw16;

    float acc[8] = {0.f, 0.f, 0.f, 0.f, 0.f, 0.f, 0.f, 0.f};
    int i = beg;
    for (; i + 3 < end; i += 4) {
        int s0 = g_sidx[i], s1 = g_sidx[i + 1], s2 = g_sidx[i + 2], s3 = g_sidx[i + 3];
        uint4 v0 = xw[(size_t)s0 * 64 + t];
        uint4 v1 = xw[(size_t)s1 * 64 + t];
        uint4 v2 = xw[(size_t)s2 * 64 + t];
        uint4 v3 = xw[(size_t)s3 * 64 + t];
        addv(acc, v0);
        addv(acc, v1);
        addv(acc, v2);
        addv(acc, v3);
    }
    for (; i < end; i++) {
        uint4 v0 = xw[(size_t)g_sidx[i] * 64 + t];
        addv(acc, v0);
    }
    float cs = (n > 0) ? rsqrtf((float)n) : 0.f;
    float4 b0 = ((const float4*)bias)[t * 2];
    float4 b1 = ((const float4*)bias)[t * 2 + 1];
    float4 o0 = make_float4(acc[0] * cs + b0.x, acc[1] * cs + b0.y,
                            acc[2] * cs + b0.z, acc[3] * cs + b0.w);
    float4 o1 = make_float4(acc[4] * cs + b1.x, acc[5] * cs + b1.y,
                            acc[6] * cs + b1.z, acc[7] * cs + b1.w);
    ((float4*)out)[(size_t)d * 128 + t * 2] = o0;
    ((float4*)out)[(size_t)d * 128 + t * 2 + 1] = o1;
}

// ---------------- launch ----------------
extern "C" void kernel_launch(void* const* d_in, const int* in_sizes, int n_in,
                              void* d_out, int out_size) {
    const float* x = (const float*)d_in[0];
    const float* w = (const float*)d_in[1];
    const float* bias = (const float*)d_in[2];
    const void* ei = d_in[3];
    float* out = (float*)d_out;

    k_init<<<(N_GENES + 255) / 256, 256>>>((const int*)ei);
    k_degree<<<(N_EDGES + 255) / 256, 256>>>(ei);
    k_compact_scan<<<21, 1024>>>();
    k_split_x<<<MB, 256>>>(x);
    k_split_w<<<512, 256>>>(w);
    k_place<<<(N_EDGES + 255) / 256, 256>>>(ei);

    dim3 gemm_grid(OUT_C / 128, MROWS / 128);
    k_gemm<<<gemm_grid, 256>>>();

    k_aggregate<<<N_DRUGS, 64>>>(bias, out);
}